// round 15
// baseline (speedup 1.0000x reference)
#include <cuda_runtime.h>
#include <cuda_fp16.h>
#include <math.h>
#include <stdint.h>

// ---------------------------------------------------------------------------
// DCN layer, fused single-pass: mma.sync fp16 2-split (A = hi+lo, B = hi).
//   k_prep      : weight fragment packing (deform + offconv)
//   k_prep_feat : feat=concat(xf,xi) -> fp16 channel-pair packed u32
//   k_fused     : per (row,b) block: offconv phase (om -> SMEM) then
//                 deform phase (R12 bodies unchanged; no g_om round-trip)
// Error model: dropped a*b_lo term (2^-12) => rel err ~2.7e-4 (R12-identical).
// B=4, Cin=64, Cout=128, H=W=128, K=9, stride=1, pad=1, dil=1
// ---------------------------------------------------------------------------

#define B_   4
#define C_   64
#define O_   128
#define H_   128
#define W_   128
#define HW_  (H_*W_)

// ---- scratch --------------------------------------------------------------
// deform weights, A-frag: ((((tap*2+split)*4+ks)*8+wt)*32+lane)*4+reg  (u32=2 fp16)
__device__ __align__(16) uint32_t g_wfrag[9 * 2 * 4 * 8 * 32 * 4];
// offconv weights, A-frag: ((((tap*2+split)*8+ks)*2+mi)*32+lane)*4+reg
__device__ __align__(16) uint32_t g_wofrag[9 * 2 * 8 * 2 * 32 * 4];
// feat fp16, channel-pair packed: [b][c2=64][y][x]
__device__ __align__(16) uint32_t g_fh2[B_ * 64 * HW_];

// ---- SMEM arena layout (bytes) --------------------------------------------
#define VS2      134                       // offconv slab stride (halves)
#define VSTRIDE  74                        // deform vsh stride (halves)
#define A_SLAB   0                         // 130*134*2 = 34840 (also deform vsh)
#define A_OM     34848                     // 128*29*4  = 14848
#define A_CW     49696                     // 4*128*4   = 2048
#define A_COF    51744                     // 4*128*4   = 2048
#define A_TOTAL  53792

// ---- helpers --------------------------------------------------------------
__device__ __forceinline__ void mma_f16(float* d, const uint32_t* a,
                                        uint32_t b0, uint32_t b1) {
    asm("mma.sync.aligned.m16n8k16.row.col.f32.f16.f16.f32 "
        "{%0,%1,%2,%3}, {%4,%5,%6,%7}, {%8,%9}, {%0,%1,%2,%3};"
        : "+f"(d[0]), "+f"(d[1]), "+f"(d[2]), "+f"(d[3])
        : "r"(a[0]), "r"(a[1]), "r"(a[2]), "r"(a[3]), "r"(b0), "r"(b1));
}
__device__ __forceinline__ uint32_t f16x2(float v0, float v1) {
    __half2 h;
    h.x = __float2half(v0);
    h.y = __float2half(v1);
    return *(uint32_t*)&h;
}

// ---------------------------------------------------------------------------
// Prep: weight fragment packing (fp16 hi + fp16 residual)
// ---------------------------------------------------------------------------
__global__ void k_prep(const float* __restrict__ w, const float* __restrict__ w_om) {
    int i = blockIdx.x * blockDim.x + threadIdx.x;
    if (i < 9 * 2 * 4 * 8 * 32 * 4) {
        int reg  = i & 3;
        int lane = (i >> 2) & 31;
        int wt   = (i >> 7) & 7;
        int ks   = (i >> 10) & 3;
        int split= (i >> 12) & 1;
        int tap  = i >> 13;
        int gid = lane >> 2, tid4 = lane & 3;
        int row  = gid + ((reg & 1) ? 8 : 0);
        int colb = 2 * tid4 + ((reg & 2) ? 8 : 0);
        int o = wt * 16 + row;
        int c0 = ks * 16 + colb;
        float w0 = w[(o * C_ + c0) * 9 + tap];
        float w1 = w[(o * C_ + c0 + 1) * 9 + tap];
        float h0 = __half2float(__float2half(w0));
        float h1 = __half2float(__float2half(w1));
        g_wfrag[i] = (split == 0) ? f16x2(h0, h1) : f16x2(w0 - h0, w1 - h1);
    }
    if (i < 9 * 2 * 8 * 2 * 32 * 4) {
        int reg  = i & 3;
        int lane = (i >> 2) & 31;
        int mi   = (i >> 7) & 1;
        int ks   = (i >> 8) & 7;
        int split= (i >> 11) & 1;
        int tap  = i >> 12;
        int gid = lane >> 2, tid4 = lane & 3;
        int row  = gid + ((reg & 1) ? 8 : 0);
        int colb = 2 * tid4 + ((reg & 2) ? 8 : 0);
        int o = mi * 16 + row;
        int c0 = ks * 16 + colb;
        float w0 = 0.f, w1 = 0.f;
        if (o < 27) {
            w0 = w_om[(o * 128 + c0) * 9 + tap];
            w1 = w_om[(o * 128 + c0 + 1) * 9 + tap];
        }
        float h0 = __half2float(__float2half(w0));
        float h1 = __half2float(__float2half(w1));
        g_wofrag[i] = (split == 0) ? f16x2(h0, h1) : f16x2(w0 - h0, w1 - h1);
    }
}

// ---------------------------------------------------------------------------
// Prep: feat -> fp16 channel-pair packed (for offconv B tiles).
// ---------------------------------------------------------------------------
__global__ __launch_bounds__(256) void k_prep_feat(
    const float* __restrict__ xf, const float* __restrict__ xi)
{
    long base = ((long)blockIdx.x * 256 + threadIdx.x) * 4;  // u32 index
    int b   = (int)(base >> 20);
    int c2  = (int)(base >> 14) & 63;
    int off = (int)base & 16383;
    int c0 = 2 * c2, c1 = c0 + 1;
    const float* s0 = (c0 < C_) ? (xf + (((long)(b * C_ + c0)) << 14) + off)
                                : (xi + (((long)(b * C_ + c0 - C_)) << 14) + off);
    const float* s1 = (c1 < C_) ? (xf + (((long)(b * C_ + c1)) << 14) + off)
                                : (xi + (((long)(b * C_ + c1 - C_)) << 14) + off);
    float4 a = *(const float4*)s0;
    float4 c = *(const float4*)s1;
    uint4 r;
    r.x = f16x2(a.x, c.x); r.y = f16x2(a.y, c.y);
    r.z = f16x2(a.z, c.z); r.w = f16x2(a.w, c.w);
    *(uint4*)&g_fh2[base] = r;
}

// ---------------------------------------------------------------------------
// Fused kernel: one block = one (row y, batch b).
// Phase 1 (R12 offconv body): om for row y -> SMEM [128][29] fp32.
// Phase 2 (R12 deform body): 9 taps of gather + mma, coords read om SMEM.
// ---------------------------------------------------------------------------
__global__ __launch_bounds__(256, 2) void k_fused(
    const float* __restrict__ x, const float* __restrict__ bias,
    const float* __restrict__ b_om, float* __restrict__ out)
{
    extern __shared__ __align__(16) char arena[];
    __half*   vh   = (__half*)(arena + A_SLAB);
    uint32_t* vhu  = (uint32_t*)vh;
    float*    om   = (float*)(arena + A_OM);      // [128][29]
    float*    cw   = (float*)(arena + A_CW);      // [4][128]
    int*      cof  = (int*)(arena + A_COF);       // [4][128]
    uint32_t* vshu = (uint32_t*)(arena + A_SLAB); // deform vsh (reuse slab)

    const int t    = threadIdx.x;
    const int lane = t & 31;
    const int wid  = t >> 5;
    const int gid  = lane >> 2;
    const int tid4 = lane & 3;
    const int y    = blockIdx.x;
    const int b    = blockIdx.y;

    // ======================= Phase 1: offset/mask conv ======================
    {
        const int mi = wid & 1;
        const int nb = (wid >> 1) * 32;

        if (t < VS2) {
            vh[t] = __float2half(0.f);
            vh[129 * VS2 + t] = __float2half(0.f);
        }

        float acc[4][4];
#pragma unroll
        for (int nt = 0; nt < 4; nt++)
#pragma unroll
            for (int q = 0; q < 4; q++) acc[nt][q] = 0.f;

        for (int dy = 0; dy < 3; dy++) {
            __syncthreads();
            {
                const int p   = t & 127;
                const int c2b = (t >> 7) * 32;
                const int ysrc = y + dy - 1;
                uint32_t* rowd = vhu + (p + 1) * (VS2 / 2) + c2b;
                if (ysrc >= 0 && ysrc < H_) {
                    const uint32_t* s = g_fh2 + (((long)(b * 64 + c2b)) << 14) + (ysrc << 7) + p;
#pragma unroll 8
                    for (int j = 0; j < 32; j++)
                        rowd[j] = s[(long)j << 14];
                } else {
#pragma unroll
                    for (int j = 0; j < 32; j++) rowd[j] = 0u;
                }
            }
            __syncthreads();

#pragma unroll
            for (int dx = 0; dx < 3; dx++) {
                const int tap = dy * 3 + dx;
                const uint32_t* wf_h = g_wofrag + ((((tap * 2 + 0) * 8) * 2 + mi) * 32 + lane) * 4;
                const uint32_t* wf_l = g_wofrag + ((((tap * 2 + 1) * 8) * 2 + mi) * 32 + lane) * 4;
#pragma unroll
                for (int ks = 0; ks < 8; ks++) {
                    uint4 ahv = *(const uint4*)(wf_h + ks * (2 * 32 * 4));
                    uint4 alv = *(const uint4*)(wf_l + ks * (2 * 32 * 4));
                    uint32_t ah[4] = {ahv.x, ahv.y, ahv.z, ahv.w};
                    uint32_t al[4] = {alv.x, alv.y, alv.z, alv.w};
#pragma unroll
                    for (int nt = 0; nt < 4; nt++) {
                        const int row = nb + nt * 8 + gid + dx;
                        const int ad = row * (VS2 / 2) + ks * 8 + tid4;
                        uint32_t b0 = vhu[ad];
                        uint32_t b1 = vhu[ad + 4];
                        mma_f16(acc[nt], ah, b0, b1);
                        mma_f16(acc[nt], al, b0, b1);
                    }
                }
            }
        }

        // epilogue -> om SMEM
        const int r0 = mi * 16 + gid;
        const int r1 = r0 + 8;
        const float bo0 = b_om[r0];
        const float bo1 = (r1 < 27) ? b_om[r1] : 0.f;
#pragma unroll
        for (int nt = 0; nt < 4; nt++) {
            const int p = nb + nt * 8 + 2 * tid4;
            float v0 = acc[nt][0] + bo0, v1 = acc[nt][1] + bo0;
            float v2 = acc[nt][2] + bo1, v3 = acc[nt][3] + bo1;
            if (r0 >= 18) { v0 = 1.f / (1.f + expf(-v0)); v1 = 1.f / (1.f + expf(-v1)); }
            if (r1 >= 18) { v2 = 1.f / (1.f + expf(-v2)); v3 = 1.f / (1.f + expf(-v3)); }
            om[p * 29 + r0]       = v0;
            om[(p + 1) * 29 + r0] = v1;
            if (r1 < 27) {
                om[p * 29 + r1]       = v2;
                om[(p + 1) * 29 + r1] = v3;
            }
        }
    }
    __syncthreads();   // om visible to all; slab free for reuse as vsh

    // ========================= Phase 2: deform conv =========================
    {
        const float* xb = x + b * (C_ * HW_);

        float acc[16][4];
#pragma unroll
        for (int pt = 0; pt < 16; pt++)
#pragma unroll
            for (int q = 0; q < 4; q++) acc[pt][q] = 0.f;

        for (int k = 0; k < 9; k++) {
            // --- coords: clamped corners + mask-premultiplied weights ---
            if (t < 128) {
                const int p = t;
                const float* omp = om + p * 29;
                float dy = omp[2 * k], dx = omp[2 * k + 1], m = omp[18 + k];
                float py  = (float)(y + k / 3 - 1) + dy;
                float pxf = (float)(p + k % 3 - 1) + dx;
                float fy = floorf(py), fx = floorf(pxf);
                int iy = (int)fy, ix = (int)fx;
                float wy = py - fy, wx = pxf - fx;
                int iy1 = iy + 1, ix1 = ix + 1;
                bool vy0 = (iy  >= 0) & (iy  < H_);
                bool vy1 = (iy1 >= 0) & (iy1 < H_);
                bool vx0 = (ix  >= 0) & (ix  < W_);
                bool vx1 = (ix1 >= 0) & (ix1 < W_);
                int cy0 = min(max(iy,  0), H_ - 1), cy1 = min(max(iy1, 0), H_ - 1);
                int cx0 = min(max(ix,  0), W_ - 1), cx1 = min(max(ix1, 0), W_ - 1);
                cof[0 * 128 + p] = cy0 * W_ + cx0;
                cof[1 * 128 + p] = cy0 * W_ + cx1;
                cof[2 * 128 + p] = cy1 * W_ + cx0;
                cof[3 * 128 + p] = cy1 * W_ + cx1;
                cw[0 * 128 + p] = (vy0 & vx0) ? (1.f - wy) * (1.f - wx) * m : 0.f;
                cw[1 * 128 + p] = (vy0 & vx1) ? (1.f - wy) * wx         * m : 0.f;
                cw[2 * 128 + p] = (vy1 & vx0) ? wy         * (1.f - wx) * m : 0.f;
                cw[3 * 128 + p] = (vy1 & vx1) ? wy         * wx         * m : 0.f;
            }
            __syncthreads();

            // --- gather: thread = (pixel, 32-ch half); fp32 -> fp16 ---
            {
                const int p  = t & 127;
                const int c0 = (t >> 7) * 32;
                const int o00 = cof[0 * 128 + p], o01 = cof[1 * 128 + p];
                const int o10 = cof[2 * 128 + p], o11 = cof[3 * 128 + p];
                const float w00 = cw[0 * 128 + p], w01 = cw[1 * 128 + p];
                const float w10 = cw[2 * 128 + p], w11 = cw[3 * 128 + p];
                const float* pc = xb + (c0 << 14);
                uint32_t* bh = vshu + p * (VSTRIDE / 2) + (c0 >> 1);
#pragma unroll 8
                for (int j = 0; j < 32; j += 2) {
                    float v0 = fmaf(w00, pc[o00], fmaf(w01, pc[o01],
                               fmaf(w10, pc[o10], w11 * pc[o11])));
                    const float* pc1 = pc + HW_;
                    float v1 = fmaf(w00, pc1[o00], fmaf(w01, pc1[o01],
                               fmaf(w10, pc1[o10], w11 * pc1[o11])));
                    bh[j >> 1] = f16x2(v0, v1);
                    pc += 2 * HW_;
                }
            }
            __syncthreads();

            // --- mma: 2 products, K = 64 ch = 4 ksteps ---
            {
                const uint32_t* wf_h = g_wfrag + ((((k * 2 + 0) * 4) * 8 + wid) * 32 + lane) * 4;
                const uint32_t* wf_l = g_wfrag + ((((k * 2 + 1) * 4) * 8 + wid) * 32 + lane) * 4;
#pragma unroll
                for (int ks = 0; ks < 4; ks++) {
                    uint4 ahv = *(const uint4*)(wf_h + ks * (8 * 32 * 4));
                    uint4 alv = *(const uint4*)(wf_l + ks * (8 * 32 * 4));
                    uint32_t ah[4] = {ahv.x, ahv.y, ahv.z, ahv.w};
                    uint32_t al[4] = {alv.x, alv.y, alv.z, alv.w};
#pragma unroll
                    for (int pt = 0; pt < 16; pt++) {
                        const int ad = (pt * 8 + gid) * (VSTRIDE / 2) + ks * 8 + tid4;
                        uint32_t b0 = vshu[ad];
                        uint32_t b1 = vshu[ad + 4];
                        mma_f16(acc[pt], ah, b0, b1);
                        mma_f16(acc[pt], al, b0, b1);
                    }
                }
            }
            __syncthreads();
        }

        // --- epilogue: +bias, float2 stores ---
        const int o0 = wid * 16 + gid;
        const int o1 = o0 + 8;
        const float bo0 = bias[o0];
        const float bo1 = bias[o1];
        float* r0 = out + (((long)(b * O_ + o0) * H_ + y) << 7);
        float* r1 = out + (((long)(b * O_ + o1) * H_ + y) << 7);
#pragma unroll
        for (int pt = 0; pt < 16; pt++) {
            const int p = pt * 8 + 2 * tid4;
            float2 v0 = make_float2(acc[pt][0] + bo0, acc[pt][1] + bo0);
            float2 v1 = make_float2(acc[pt][2] + bo1, acc[pt][3] + bo1);
            *(float2*)(r0 + p) = v0;
            *(float2*)(r1 + p) = v1;
        }
    }
}

// ---------------------------------------------------------------------------
extern "C" void kernel_launch(void* const* d_in, const int* in_sizes, int n_in,
                              void* d_out, int out_size)
{
    const float* input_feat = (const float*)d_in[0];  // [4,64,128,128]
    const float* inter      = (const float*)d_in[1];  // [4,64,128,128]
    const float* weight     = (const float*)d_in[2];  // [128,64,3,3]
    const float* bias       = (const float*)d_in[3];  // [128]
    const float* w_om       = (const float*)d_in[4];  // [27,128,3,3]
    const float* b_om       = (const float*)d_in[5];  // [27]
    float* out = (float*)d_out;                       // [4,128,128,128]

    static int smem_set = 0;
    if (!smem_set) {
        cudaFuncSetAttribute(k_fused,
                             cudaFuncAttributeMaxDynamicSharedMemorySize, A_TOTAL);
        smem_set = 1;
    }

    k_prep<<<288, 256>>>(weight, w_om);
    k_prep_feat<<<4096, 256>>>(input_feat, inter);
    k_fused<<<dim3(128, 4), 256, A_TOTAL>>>(input_feat, bias, b_om, out);
}

// round 16
// speedup vs baseline: 1.2156x; 1.2156x over previous
#include <cuda_runtime.h>
#include <cuda_fp16.h>
#include <math.h>
#include <stdint.h>

// ---------------------------------------------------------------------------
// DCN layer via mma.sync fp16 2-split (A = hi+lo fp16, B = single fp16).
// R12 structure exactly; single change: deform gather reads fp16 channel-last
// g_xh (half the loads / sectors of the fp32 plane gather).
//   k_prep       : weight fragment packing (deform + offconv)
//   k_prep_feat  : feat=concat(xf,xi) -> fp16 channel-pair packed u32
//   k_prep_xh    : input_feat -> fp16 channel-last [b][y][x][c2]
//   k_offconv_mma: offset/mask conv, 2-product mma (R12, unchanged)
//   k_deform_mma : deformable conv, 2-product mma (R12 tiling, fp16 gather)
// Error: dropped a*b_lo (2^-12) + fp16 corners (2^-11) => ~3.4e-4 (R14-measured).
// B=4, Cin=64, Cout=128, H=W=128, K=9, stride=1, pad=1, dil=1
// ---------------------------------------------------------------------------

#define B_   4
#define C_   64
#define O_   128
#define H_   128
#define W_   128
#define HW_  (H_*W_)

// ---- scratch --------------------------------------------------------------
__device__ float g_om[B_ * H_ * W_ * 28];   // per-pixel [dy0,dx0,..,dy8,dx8,m0..m8]
// deform weights, A-frag: ((((tap*2+split)*4+ks)*8+wt)*32+lane)*4+reg  (u32=2 fp16)
__device__ __align__(16) uint32_t g_wfrag[9 * 2 * 4 * 8 * 32 * 4];
// offconv weights, A-frag: ((((tap*2+split)*8+ks)*2+mi)*32+lane)*4+reg
__device__ __align__(16) uint32_t g_wofrag[9 * 2 * 8 * 2 * 32 * 4];
// feat fp16, channel-pair packed: [b][c2=64][y][x] (offconv)
__device__ __align__(16) uint32_t g_fh2[B_ * 64 * HW_];
// input_feat fp16 channel-last: [b][y][x][c2=32 u32] (deform gather)
__device__ __align__(16) uint32_t g_xh[(long)B_ * HW_ * 32];

// ---- helpers --------------------------------------------------------------
__device__ __forceinline__ void mma_f16(float* d, const uint32_t* a,
                                        uint32_t b0, uint32_t b1) {
    asm("mma.sync.aligned.m16n8k16.row.col.f32.f16.f16.f32 "
        "{%0,%1,%2,%3}, {%4,%5,%6,%7}, {%8,%9}, {%0,%1,%2,%3};"
        : "+f"(d[0]), "+f"(d[1]), "+f"(d[2]), "+f"(d[3])
        : "r"(a[0]), "r"(a[1]), "r"(a[2]), "r"(a[3]), "r"(b0), "r"(b1));
}
__device__ __forceinline__ uint32_t f16x2(float v0, float v1) {
    __half2 h;
    h.x = __float2half(v0);
    h.y = __float2half(v1);
    return *(uint32_t*)&h;
}
__device__ __forceinline__ float2 h2f2(uint32_t u) {
    return __half22float2(*(__half2*)&u);
}

// ---------------------------------------------------------------------------
// Prep: weight fragment packing (fp16 hi + fp16 residual)
// ---------------------------------------------------------------------------
__global__ void k_prep(const float* __restrict__ w, const float* __restrict__ w_om) {
    int i = blockIdx.x * blockDim.x + threadIdx.x;
    if (i < 9 * 2 * 4 * 8 * 32 * 4) {
        int reg  = i & 3;
        int lane = (i >> 2) & 31;
        int wt   = (i >> 7) & 7;
        int ks   = (i >> 10) & 3;
        int split= (i >> 12) & 1;
        int tap  = i >> 13;
        int gid = lane >> 2, tid4 = lane & 3;
        int row  = gid + ((reg & 1) ? 8 : 0);
        int colb = 2 * tid4 + ((reg & 2) ? 8 : 0);
        int o = wt * 16 + row;
        int c0 = ks * 16 + colb;
        float w0 = w[(o * C_ + c0) * 9 + tap];
        float w1 = w[(o * C_ + c0 + 1) * 9 + tap];
        float h0 = __half2float(__float2half(w0));
        float h1 = __half2float(__float2half(w1));
        g_wfrag[i] = (split == 0) ? f16x2(h0, h1) : f16x2(w0 - h0, w1 - h1);
    }
    if (i < 9 * 2 * 8 * 2 * 32 * 4) {
        int reg  = i & 3;
        int lane = (i >> 2) & 31;
        int mi   = (i >> 7) & 1;
        int ks   = (i >> 8) & 7;
        int split= (i >> 11) & 1;
        int tap  = i >> 12;
        int gid = lane >> 2, tid4 = lane & 3;
        int row  = gid + ((reg & 1) ? 8 : 0);
        int colb = 2 * tid4 + ((reg & 2) ? 8 : 0);
        int o = mi * 16 + row;
        int c0 = ks * 16 + colb;
        float w0 = 0.f, w1 = 0.f;
        if (o < 27) {
            w0 = w_om[(o * 128 + c0) * 9 + tap];
            w1 = w_om[(o * 128 + c0 + 1) * 9 + tap];
        }
        float h0 = __half2float(__float2half(w0));
        float h1 = __half2float(__float2half(w1));
        g_wofrag[i] = (split == 0) ? f16x2(h0, h1) : f16x2(w0 - h0, w1 - h1);
    }
}

// ---------------------------------------------------------------------------
// Prep: feat -> fp16 channel-pair packed (for offconv B tiles).
// ---------------------------------------------------------------------------
__global__ __launch_bounds__(256) void k_prep_feat(
    const float* __restrict__ xf, const float* __restrict__ xi)
{
    long base = ((long)blockIdx.x * 256 + threadIdx.x) * 4;  // u32 index
    int b   = (int)(base >> 20);
    int c2  = (int)(base >> 14) & 63;
    int off = (int)base & 16383;
    int c0 = 2 * c2, c1 = c0 + 1;
    const float* s0 = (c0 < C_) ? (xf + (((long)(b * C_ + c0)) << 14) + off)
                                : (xi + (((long)(b * C_ + c0 - C_)) << 14) + off);
    const float* s1 = (c1 < C_) ? (xf + (((long)(b * C_ + c1)) << 14) + off)
                                : (xi + (((long)(b * C_ + c1 - C_)) << 14) + off);
    float4 a = *(const float4*)s0;
    float4 c = *(const float4*)s1;
    uint4 r;
    r.x = f16x2(a.x, c.x); r.y = f16x2(a.y, c.y);
    r.z = f16x2(a.z, c.z); r.w = f16x2(a.w, c.w);
    *(uint4*)&g_fh2[base] = r;
}

// ---------------------------------------------------------------------------
// Prep: input_feat -> fp16 channel-last [b][y][x][c2] (deform gather).
// ---------------------------------------------------------------------------
__global__ __launch_bounds__(256) void k_prep_xh(const float* __restrict__ xf)
{
    __shared__ float sm[128][65];   // [p][c]
    const int y = blockIdx.x;
    const int b = blockIdx.y;
    for (int i = threadIdx.x; i < 64 * 128; i += 256) {
        int c = i >> 7, p = i & 127;
        sm[p][c] = xf[(((long)(b * C_ + c)) << 14) + (y << 7) + p];
    }
    __syncthreads();
    uint32_t* dst = g_xh + (((long)((b << 7) + y)) << 7) * 32;
    for (int i = threadIdx.x; i < 128 * 32; i += 256) {
        int p = i >> 5, c2 = i & 31;
        dst[i] = f16x2(sm[p][2 * c2], sm[p][2 * c2 + 1]);
    }
}

// ---------------------------------------------------------------------------
// Kernel 1: offset/mask conv via mma.sync fp16 2-product (R12, unchanged).
// ---------------------------------------------------------------------------
#define VS2 134

__global__ __launch_bounds__(256, 2) void k_offconv_mma(
    const float* __restrict__ b_om)
{
    __shared__ __align__(16) __half vh[130 * VS2];

    const int t    = threadIdx.x;
    const int lane = t & 31;
    const int wid  = t >> 5;
    const int gid  = lane >> 2;
    const int tid4 = lane & 3;
    const int y    = blockIdx.x;
    const int b    = blockIdx.y;

    const int mi = wid & 1;
    const int nb = (wid >> 1) * 32;

    uint32_t* vhu = (uint32_t*)vh;

    if (t < VS2) {
        vh[t] = __float2half(0.f);
        vh[129 * VS2 + t] = __float2half(0.f);
    }

    float acc[4][4];
#pragma unroll
    for (int nt = 0; nt < 4; nt++)
#pragma unroll
        for (int q = 0; q < 4; q++) acc[nt][q] = 0.f;

    for (int dy = 0; dy < 3; dy++) {
        __syncthreads();
        {
            const int p   = t & 127;
            const int c2b = (t >> 7) * 32;
            const int ysrc = y + dy - 1;
            uint32_t* rowd = vhu + (p + 1) * (VS2 / 2) + c2b;
            if (ysrc >= 0 && ysrc < H_) {
                const uint32_t* s = g_fh2 + (((long)(b * 64 + c2b)) << 14) + (ysrc << 7) + p;
#pragma unroll 8
                for (int j = 0; j < 32; j++)
                    rowd[j] = s[(long)j << 14];
            } else {
#pragma unroll
                for (int j = 0; j < 32; j++) rowd[j] = 0u;
            }
        }
        __syncthreads();

#pragma unroll
        for (int dx = 0; dx < 3; dx++) {
            const int tap = dy * 3 + dx;
            const uint32_t* wf_h = g_wofrag + ((((tap * 2 + 0) * 8) * 2 + mi) * 32 + lane) * 4;
            const uint32_t* wf_l = g_wofrag + ((((tap * 2 + 1) * 8) * 2 + mi) * 32 + lane) * 4;
#pragma unroll
            for (int ks = 0; ks < 8; ks++) {
                uint4 ahv = *(const uint4*)(wf_h + ks * (2 * 32 * 4));
                uint4 alv = *(const uint4*)(wf_l + ks * (2 * 32 * 4));
                uint32_t ah[4] = {ahv.x, ahv.y, ahv.z, ahv.w};
                uint32_t al[4] = {alv.x, alv.y, alv.z, alv.w};
#pragma unroll
                for (int nt = 0; nt < 4; nt++) {
                    const int row = nb + nt * 8 + gid + dx;
                    const int ad = row * (VS2 / 2) + ks * 8 + tid4;
                    uint32_t b0 = vhu[ad];
                    uint32_t b1 = vhu[ad + 4];
                    mma_f16(acc[nt], ah, b0, b1);
                    mma_f16(acc[nt], al, b0, b1);
                }
            }
        }
    }

    const int r0 = mi * 16 + gid;
    const int r1 = r0 + 8;
    const float bo0 = b_om[r0];
    const float bo1 = (r1 < 27) ? b_om[r1] : 0.f;
    float* omb = g_om + ((long)((b * H_ + y) * W_)) * 28;
#pragma unroll
    for (int nt = 0; nt < 4; nt++) {
        const int p = nb + nt * 8 + 2 * tid4;
        float v0 = acc[nt][0] + bo0, v1 = acc[nt][1] + bo0;
        float v2 = acc[nt][2] + bo1, v3 = acc[nt][3] + bo1;
        if (r0 >= 18) { v0 = 1.f / (1.f + expf(-v0)); v1 = 1.f / (1.f + expf(-v1)); }
        if (r1 >= 18) { v2 = 1.f / (1.f + expf(-v2)); v3 = 1.f / (1.f + expf(-v3)); }
        omb[(long)p * 28 + r0]       = v0;
        omb[(long)(p + 1) * 28 + r0] = v1;
        if (r1 < 27) {
            omb[(long)p * 28 + r1]       = v2;
            omb[(long)(p + 1) * 28 + r1] = v3;
        }
    }
}

// ---------------------------------------------------------------------------
// Kernel 2: deformable conv via mma.sync fp16 2-product (R12 tiling).
// Gather: thread = (pixel, 32-ch half); 4 corners x 16 consecutive u32
// channel pairs from g_xh (64 LDG.32, ~2 sectors per corner per lane).
// VSTRIDE=74 (37 u32, odd -> STS conflict-free, 2-way mma B loads).
// ---------------------------------------------------------------------------
#define VSTRIDE 74

__global__ __launch_bounds__(256, 2) void k_deform_mma(
    const float* __restrict__ bias, float* __restrict__ out)
{
    __shared__ __align__(16) __half vsh[128 * VSTRIDE];
    __shared__ float cw[4][128];
    __shared__ int   cof[4][128];

    const int t    = threadIdx.x;
    const int lane = t & 31;
    const int wid  = t >> 5;
    const int gid  = lane >> 2;
    const int tid4 = lane & 3;
    const int y    = blockIdx.x;
    const int b    = blockIdx.y;

    const uint32_t* xh = g_xh + ((long)b << 19);   // b * HW_*32
    uint32_t* vshu = (uint32_t*)vsh;

    float acc[16][4];
#pragma unroll
    for (int pt = 0; pt < 16; pt++)
#pragma unroll
        for (int q = 0; q < 4; q++) acc[pt][q] = 0.f;

    for (int k = 0; k < 9; k++) {
        // --- per-pixel coords: clamped corners + mask-premultiplied weights ---
        if (t < 128) {
            const int p = t;
            const float* omp = g_om + ((long)((b * H_ + y) * W_) + p) * 28;
            float dy = omp[2 * k], dx = omp[2 * k + 1], m = omp[18 + k];
            float py  = (float)(y + k / 3 - 1) + dy;
            float pxf = (float)(p + k % 3 - 1) + dx;
            float fy = floorf(py), fx = floorf(pxf);
            int iy = (int)fy, ix = (int)fx;
            float wy = py - fy, wx = pxf - fx;
            int iy1 = iy + 1, ix1 = ix + 1;
            bool vy0 = (iy  >= 0) & (iy  < H_);
            bool vy1 = (iy1 >= 0) & (iy1 < H_);
            bool vx0 = (ix  >= 0) & (ix  < W_);
            bool vx1 = (ix1 >= 0) & (ix1 < W_);
            int cy0 = min(max(iy,  0), H_ - 1), cy1 = min(max(iy1, 0), H_ - 1);
            int cx0 = min(max(ix,  0), W_ - 1), cx1 = min(max(ix1, 0), W_ - 1);
            cof[0][p] = cy0 * W_ + cx0;
            cof[1][p] = cy0 * W_ + cx1;
            cof[2][p] = cy1 * W_ + cx0;
            cof[3][p] = cy1 * W_ + cx1;
            cw[0][p] = (vy0 & vx0) ? (1.f - wy) * (1.f - wx) * m : 0.f;
            cw[1][p] = (vy0 & vx1) ? (1.f - wy) * wx         * m : 0.f;
            cw[2][p] = (vy1 & vx0) ? wy         * (1.f - wx) * m : 0.f;
            cw[3][p] = (vy1 & vx1) ? wy         * wx         * m : 0.f;
        }
        __syncthreads();

        // --- gather: thread = (pixel, 32-ch half); fp16 pairs, fp32 blend ---
        {
            const int p   = t & 127;
            const int c2b = (t >> 7) * 16;   // u32 pair base (16 pairs = 32 ch)
            const uint32_t* p00 = xh + cof[0][p] * 32 + c2b;
            const uint32_t* p01 = xh + cof[1][p] * 32 + c2b;
            const uint32_t* p10 = xh + cof[2][p] * 32 + c2b;
            const uint32_t* p11 = xh + cof[3][p] * 32 + c2b;
            const float w00 = cw[0][p], w01 = cw[1][p];
            const float w10 = cw[2][p], w11 = cw[3][p];
            uint32_t* dst = vshu + p * (VSTRIDE / 2) + c2b;
#pragma unroll 8
            for (int j = 0; j < 16; j++) {
                float2 a = h2f2(p00[j]);
                float2 c = h2f2(p01[j]);
                float2 d = h2f2(p10[j]);
                float2 e = h2f2(p11[j]);
                float vx = fmaf(w00, a.x, fmaf(w01, c.x, fmaf(w10, d.x, w11 * e.x)));
                float vy = fmaf(w00, a.y, fmaf(w01, c.y, fmaf(w10, d.y, w11 * e.y)));
                dst[j] = f16x2(vx, vy);
            }
        }
        __syncthreads();

        // --- mma: 2 products, K = 64 ch = 4 ksteps (R12, unchanged) ---
        {
            const uint32_t* wf_h = g_wfrag + ((((k * 2 + 0) * 4) * 8 + wid) * 32 + lane) * 4;
            const uint32_t* wf_l = g_wfrag + ((((k * 2 + 1) * 4) * 8 + wid) * 32 + lane) * 4;
#pragma unroll
            for (int ks = 0; ks < 4; ks++) {
                uint4 ahv = *(const uint4*)(wf_h + ks * (8 * 32 * 4));
                uint4 alv = *(const uint4*)(wf_l + ks * (8 * 32 * 4));
                uint32_t ah[4] = {ahv.x, ahv.y, ahv.z, ahv.w};
                uint32_t al[4] = {alv.x, alv.y, alv.z, alv.w};
#pragma unroll
                for (int pt = 0; pt < 16; pt++) {
                    const int ad = (pt * 8 + gid) * (VSTRIDE / 2) + ks * 8 + tid4;
                    uint32_t b0 = vshu[ad];
                    uint32_t b1 = vshu[ad + 4];
                    mma_f16(acc[pt], ah, b0, b1);
                    mma_f16(acc[pt], al, b0, b1);
                }
            }
        }
        __syncthreads();
    }

    // --- epilogue: +bias, float2 stores ---
    const int o0 = wid * 16 + gid;
    const int o1 = o0 + 8;
    const float bo0 = bias[o0];
    const float bo1 = bias[o1];
    float* r0 = out + (((long)(b * O_ + o0) * H_ + y) << 7);
    float* r1 = out + (((long)(b * O_ + o1) * H_ + y) << 7);
#pragma unroll
    for (int pt = 0; pt < 16; pt++) {
        const int p = pt * 8 + 2 * tid4;
        float2 v0 = make_float2(acc[pt][0] + bo0, acc[pt][1] + bo0);
        float2 v1 = make_float2(acc[pt][2] + bo1, acc[pt][3] + bo1);
        *(float2*)(r0 + p) = v0;
        *(float2*)(r1 + p) = v1;
    }
}

// ---------------------------------------------------------------------------
extern "C" void kernel_launch(void* const* d_in, const int* in_sizes, int n_in,
                              void* d_out, int out_size)
{
    const float* input_feat = (const float*)d_in[0];  // [4,64,128,128]
    const float* inter      = (const float*)d_in[1];  // [4,64,128,128]
    const float* weight     = (const float*)d_in[2];  // [128,64,3,3]
    const float* bias       = (const float*)d_in[3];  // [128]
    const float* w_om       = (const float*)d_in[4];  // [27,128,3,3]
    const float* b_om       = (const float*)d_in[5];  // [27]
    float* out = (float*)d_out;                       // [4,128,128,128]

    k_prep<<<288, 256>>>(weight, w_om);
    k_prep_feat<<<4096, 256>>>(input_feat, inter);
    k_prep_xh<<<dim3(128, 4), 256>>>(input_feat);
    k_offconv_mma<<<dim3(128, 4), 256>>>(b_om);
    k_deform_mma<<<dim3(128, 4), 256>>>(bias, out);
}

// round 17
// speedup vs baseline: 1.3727x; 1.1292x over previous
#include <cuda_runtime.h>
#include <cuda_fp16.h>
#include <math.h>
#include <stdint.h>

// ---------------------------------------------------------------------------
// DCN layer via mma.sync fp16 2-split (A = hi+lo fp16, B = single fp16).
// R12 arithmetic exactly; single structural change in k_deform_mma:
//   - per-thread inline coords (no coords phase / SMEM / barrier)
//   - double-buffered vsh => ONE __syncthreads per tap (was three)
// Error model: dropped a*b_lo term (2^-12) => rel err ~2.7e-4 (R12-identical).
// B=4, Cin=64, Cout=128, H=W=128, K=9, stride=1, pad=1, dil=1
// ---------------------------------------------------------------------------

#define B_   4
#define C_   64
#define O_   128
#define H_   128
#define W_   128
#define HW_  (H_*W_)

// ---- scratch --------------------------------------------------------------
__device__ float g_om[B_ * H_ * W_ * 28];   // per-pixel [dy0,dx0,..,dy8,dx8,m0..m8]
// deform weights, A-frag: ((((tap*2+split)*4+ks)*8+wt)*32+lane)*4+reg  (u32=2 fp16)
__device__ __align__(16) uint32_t g_wfrag[9 * 2 * 4 * 8 * 32 * 4];
// offconv weights, A-frag: ((((tap*2+split)*8+ks)*2+mi)*32+lane)*4+reg
__device__ __align__(16) uint32_t g_wofrag[9 * 2 * 8 * 2 * 32 * 4];
// feat fp16, channel-pair packed: [b][c2=64][y][x]
__device__ __align__(16) uint32_t g_fh2[B_ * 64 * HW_];

// ---- helpers --------------------------------------------------------------
__device__ __forceinline__ void mma_f16(float* d, const uint32_t* a,
                                        uint32_t b0, uint32_t b1) {
    asm("mma.sync.aligned.m16n8k16.row.col.f32.f16.f16.f32 "
        "{%0,%1,%2,%3}, {%4,%5,%6,%7}, {%8,%9}, {%0,%1,%2,%3};"
        : "+f"(d[0]), "+f"(d[1]), "+f"(d[2]), "+f"(d[3])
        : "r"(a[0]), "r"(a[1]), "r"(a[2]), "r"(a[3]), "r"(b0), "r"(b1));
}
__device__ __forceinline__ uint32_t f16x2(float v0, float v1) {
    __half2 h;
    h.x = __float2half(v0);
    h.y = __float2half(v1);
    return *(uint32_t*)&h;
}

// ---------------------------------------------------------------------------
// Prep: weight fragment packing (fp16 hi + fp16 residual)
// ---------------------------------------------------------------------------
__global__ void k_prep(const float* __restrict__ w, const float* __restrict__ w_om) {
    int i = blockIdx.x * blockDim.x + threadIdx.x;
    if (i < 9 * 2 * 4 * 8 * 32 * 4) {
        int reg  = i & 3;
        int lane = (i >> 2) & 31;
        int wt   = (i >> 7) & 7;
        int ks   = (i >> 10) & 3;
        int split= (i >> 12) & 1;
        int tap  = i >> 13;
        int gid = lane >> 2, tid4 = lane & 3;
        int row  = gid + ((reg & 1) ? 8 : 0);
        int colb = 2 * tid4 + ((reg & 2) ? 8 : 0);
        int o = wt * 16 + row;
        int c0 = ks * 16 + colb;
        float w0 = w[(o * C_ + c0) * 9 + tap];
        float w1 = w[(o * C_ + c0 + 1) * 9 + tap];
        float h0 = __half2float(__float2half(w0));
        float h1 = __half2float(__float2half(w1));
        g_wfrag[i] = (split == 0) ? f16x2(h0, h1) : f16x2(w0 - h0, w1 - h1);
    }
    if (i < 9 * 2 * 8 * 2 * 32 * 4) {
        int reg  = i & 3;
        int lane = (i >> 2) & 31;
        int mi   = (i >> 7) & 1;
        int ks   = (i >> 8) & 7;
        int split= (i >> 11) & 1;
        int tap  = i >> 12;
        int gid = lane >> 2, tid4 = lane & 3;
        int row  = gid + ((reg & 1) ? 8 : 0);
        int colb = 2 * tid4 + ((reg & 2) ? 8 : 0);
        int o = mi * 16 + row;
        int c0 = ks * 16 + colb;
        float w0 = 0.f, w1 = 0.f;
        if (o < 27) {
            w0 = w_om[(o * 128 + c0) * 9 + tap];
            w1 = w_om[(o * 128 + c0 + 1) * 9 + tap];
        }
        float h0 = __half2float(__float2half(w0));
        float h1 = __half2float(__float2half(w1));
        g_wofrag[i] = (split == 0) ? f16x2(h0, h1) : f16x2(w0 - h0, w1 - h1);
    }
}

// ---------------------------------------------------------------------------
// Prep: feat -> fp16 channel-pair packed (for offconv B tiles).
// ---------------------------------------------------------------------------
__global__ __launch_bounds__(256) void k_prep_feat(
    const float* __restrict__ xf, const float* __restrict__ xi)
{
    long base = ((long)blockIdx.x * 256 + threadIdx.x) * 4;  // u32 index
    int b   = (int)(base >> 20);
    int c2  = (int)(base >> 14) & 63;
    int off = (int)base & 16383;
    int c0 = 2 * c2, c1 = c0 + 1;
    const float* s0 = (c0 < C_) ? (xf + (((long)(b * C_ + c0)) << 14) + off)
                                : (xi + (((long)(b * C_ + c0 - C_)) << 14) + off);
    const float* s1 = (c1 < C_) ? (xf + (((long)(b * C_ + c1)) << 14) + off)
                                : (xi + (((long)(b * C_ + c1 - C_)) << 14) + off);
    float4 a = *(const float4*)s0;
    float4 c = *(const float4*)s1;
    uint4 r;
    r.x = f16x2(a.x, c.x); r.y = f16x2(a.y, c.y);
    r.z = f16x2(a.z, c.z); r.w = f16x2(a.w, c.w);
    *(uint4*)&g_fh2[base] = r;
}

// ---------------------------------------------------------------------------
// Kernel 1: offset/mask conv via mma.sync fp16 2-product (R12, unchanged).
// ---------------------------------------------------------------------------
#define VS2 134

__global__ __launch_bounds__(256, 2) void k_offconv_mma(
    const float* __restrict__ b_om)
{
    __shared__ __align__(16) __half vh[130 * VS2];

    const int t    = threadIdx.x;
    const int lane = t & 31;
    const int wid  = t >> 5;
    const int gid  = lane >> 2;
    const int tid4 = lane & 3;
    const int y    = blockIdx.x;
    const int b    = blockIdx.y;

    const int mi = wid & 1;
    const int nb = (wid >> 1) * 32;

    uint32_t* vhu = (uint32_t*)vh;

    if (t < VS2) {
        vh[t] = __float2half(0.f);
        vh[129 * VS2 + t] = __float2half(0.f);
    }

    float acc[4][4];
#pragma unroll
    for (int nt = 0; nt < 4; nt++)
#pragma unroll
        for (int q = 0; q < 4; q++) acc[nt][q] = 0.f;

    for (int dy = 0; dy < 3; dy++) {
        __syncthreads();
        {
            const int p   = t & 127;
            const int c2b = (t >> 7) * 32;
            const int ysrc = y + dy - 1;
            uint32_t* rowd = vhu + (p + 1) * (VS2 / 2) + c2b;
            if (ysrc >= 0 && ysrc < H_) {
                const uint32_t* s = g_fh2 + (((long)(b * 64 + c2b)) << 14) + (ysrc << 7) + p;
#pragma unroll 8
                for (int j = 0; j < 32; j++)
                    rowd[j] = s[(long)j << 14];
            } else {
#pragma unroll
                for (int j = 0; j < 32; j++) rowd[j] = 0u;
            }
        }
        __syncthreads();

#pragma unroll
        for (int dx = 0; dx < 3; dx++) {
            const int tap = dy * 3 + dx;
            const uint32_t* wf_h = g_wofrag + ((((tap * 2 + 0) * 8) * 2 + mi) * 32 + lane) * 4;
            const uint32_t* wf_l = g_wofrag + ((((tap * 2 + 1) * 8) * 2 + mi) * 32 + lane) * 4;
#pragma unroll
            for (int ks = 0; ks < 8; ks++) {
                uint4 ahv = *(const uint4*)(wf_h + ks * (2 * 32 * 4));
                uint4 alv = *(const uint4*)(wf_l + ks * (2 * 32 * 4));
                uint32_t ah[4] = {ahv.x, ahv.y, ahv.z, ahv.w};
                uint32_t al[4] = {alv.x, alv.y, alv.z, alv.w};
#pragma unroll
                for (int nt = 0; nt < 4; nt++) {
                    const int row = nb + nt * 8 + gid + dx;
                    const int ad = row * (VS2 / 2) + ks * 8 + tid4;
                    uint32_t b0 = vhu[ad];
                    uint32_t b1 = vhu[ad + 4];
                    mma_f16(acc[nt], ah, b0, b1);
                    mma_f16(acc[nt], al, b0, b1);
                }
            }
        }
    }

    const int r0 = mi * 16 + gid;
    const int r1 = r0 + 8;
    const float bo0 = b_om[r0];
    const float bo1 = (r1 < 27) ? b_om[r1] : 0.f;
    float* omb = g_om + ((long)((b * H_ + y) * W_)) * 28;
#pragma unroll
    for (int nt = 0; nt < 4; nt++) {
        const int p = nb + nt * 8 + 2 * tid4;
        float v0 = acc[nt][0] + bo0, v1 = acc[nt][1] + bo0;
        float v2 = acc[nt][2] + bo1, v3 = acc[nt][3] + bo1;
        if (r0 >= 18) { v0 = 1.f / (1.f + expf(-v0)); v1 = 1.f / (1.f + expf(-v1)); }
        if (r1 >= 18) { v2 = 1.f / (1.f + expf(-v2)); v3 = 1.f / (1.f + expf(-v3)); }
        omb[(long)p * 28 + r0]       = v0;
        omb[(long)(p + 1) * 28 + r0] = v1;
        if (r1 < 27) {
            omb[(long)p * 28 + r1]       = v2;
            omb[(long)(p + 1) * 28 + r1] = v3;
        }
    }
}

// ---------------------------------------------------------------------------
// Kernel 2: deformable conv, fp16 2-product mma, software-pipelined:
// inline per-thread coords + double-buffered vsh => 1 barrier per tap.
// Gather and mma bodies are arithmetic-identical to R12.
// ---------------------------------------------------------------------------
#define VSTRIDE 74

// per-thread gather for tap k: thread handles pixel p = t&127, channel half c0.
__device__ __forceinline__ void deform_gather(
    int k, int t, int y, const float* __restrict__ omrow,
    const float* __restrict__ xb, uint32_t* __restrict__ vshu)
{
    const int p  = t & 127;
    const int c0 = (t >> 7) * 32;
    const float* omp = omrow + (long)p * 28;
    float dy = omp[2 * k], dx = omp[2 * k + 1], m = omp[18 + k];
    float py  = (float)(y + k / 3 - 1) + dy;
    float pxf = (float)(p + k % 3 - 1) + dx;
    float fy = floorf(py), fx = floorf(pxf);
    int iy = (int)fy, ix = (int)fx;
    float wy = py - fy, wx = pxf - fx;
    int iy1 = iy + 1, ix1 = ix + 1;
    bool vy0 = (iy  >= 0) & (iy  < H_);
    bool vy1 = (iy1 >= 0) & (iy1 < H_);
    bool vx0 = (ix  >= 0) & (ix  < W_);
    bool vx1 = (ix1 >= 0) & (ix1 < W_);
    int cy0 = min(max(iy,  0), H_ - 1), cy1 = min(max(iy1, 0), H_ - 1);
    int cx0 = min(max(ix,  0), W_ - 1), cx1 = min(max(ix1, 0), W_ - 1);
    const int o00 = cy0 * W_ + cx0;
    const int o01 = cy0 * W_ + cx1;
    const int o10 = cy1 * W_ + cx0;
    const int o11 = cy1 * W_ + cx1;
    const float w00 = (vy0 & vx0) ? (1.f - wy) * (1.f - wx) * m : 0.f;
    const float w01 = (vy0 & vx1) ? (1.f - wy) * wx         * m : 0.f;
    const float w10 = (vy1 & vx0) ? wy         * (1.f - wx) * m : 0.f;
    const float w11 = (vy1 & vx1) ? wy         * wx         * m : 0.f;

    const float* pc = xb + (c0 << 14);
    uint32_t* bh = vshu + p * (VSTRIDE / 2) + (c0 >> 1);
#pragma unroll 8
    for (int j = 0; j < 32; j += 2) {
        float v0 = fmaf(w00, pc[o00], fmaf(w01, pc[o01],
                   fmaf(w10, pc[o10], w11 * pc[o11])));
        const float* pc1 = pc + HW_;
        float v1 = fmaf(w00, pc1[o00], fmaf(w01, pc1[o01],
                   fmaf(w10, pc1[o10], w11 * pc1[o11])));
        bh[j >> 1] = f16x2(v0, v1);
        pc += 2 * HW_;
    }
}

__global__ __launch_bounds__(256, 2) void k_deform_mma(
    const float* __restrict__ x, const float* __restrict__ bias,
    float* __restrict__ out)
{
    __shared__ __align__(16) __half vsh[2][128 * VSTRIDE];

    const int t    = threadIdx.x;
    const int lane = t & 31;
    const int wid  = t >> 5;
    const int gid  = lane >> 2;
    const int tid4 = lane & 3;
    const int y    = blockIdx.x;
    const int b    = blockIdx.y;

    const float* xb    = x + b * (C_ * HW_);
    const float* omrow = g_om + ((long)((b * H_ + y) * W_)) * 28;

    float acc[16][4];
#pragma unroll
    for (int pt = 0; pt < 16; pt++)
#pragma unroll
        for (int q = 0; q < 4; q++) acc[pt][q] = 0.f;

    // prologue: fill buffer 0
    deform_gather(0, t, y, omrow, xb, (uint32_t*)vsh[0]);

#pragma unroll 1
    for (int k = 0; k < 9; k++) {
        __syncthreads();   // buf[k&1] complete; buf[(k+1)&1] free

        // issue next tap's gather early (writes the other buffer)
        if (k < 8)
            deform_gather(k + 1, t, y, omrow, xb, (uint32_t*)vsh[(k + 1) & 1]);

        // mma on buf[k&1] (R12 body)
        {
            const uint32_t* vshu = (const uint32_t*)vsh[k & 1];
            const uint32_t* wf_h = g_wfrag + ((((k * 2 + 0) * 4) * 8 + wid) * 32 + lane) * 4;
            const uint32_t* wf_l = g_wfrag + ((((k * 2 + 1) * 4) * 8 + wid) * 32 + lane) * 4;
#pragma unroll
            for (int ks = 0; ks < 4; ks++) {
                uint4 ahv = *(const uint4*)(wf_h + ks * (8 * 32 * 4));
                uint4 alv = *(const uint4*)(wf_l + ks * (8 * 32 * 4));
                uint32_t ah[4] = {ahv.x, ahv.y, ahv.z, ahv.w};
                uint32_t al[4] = {alv.x, alv.y, alv.z, alv.w};
#pragma unroll
                for (int pt = 0; pt < 16; pt++) {
                    const int ad = (pt * 8 + gid) * (VSTRIDE / 2) + ks * 8 + tid4;
                    uint32_t b0 = vshu[ad];
                    uint32_t b1 = vshu[ad + 4];
                    mma_f16(acc[pt], ah, b0, b1);
                    mma_f16(acc[pt], al, b0, b1);
                }
            }
        }
    }

    // --- epilogue: +bias, float2 stores ---
    const int o0 = wid * 16 + gid;
    const int o1 = o0 + 8;
    const float bo0 = bias[o0];
    const float bo1 = bias[o1];
    float* r0 = out + (((long)(b * O_ + o0) * H_ + y) << 7);
    float* r1 = out + (((long)(b * O_ + o1) * H_ + y) << 7);
#pragma unroll
    for (int pt = 0; pt < 16; pt++) {
        const int p = pt * 8 + 2 * tid4;
        float2 v0 = make_float2(acc[pt][0] + bo0, acc[pt][1] + bo0);
        float2 v1 = make_float2(acc[pt][2] + bo1, acc[pt][3] + bo1);
        *(float2*)(r0 + p) = v0;
        *(float2*)(r1 + p) = v1;
    }
}

// ---------------------------------------------------------------------------
extern "C" void kernel_launch(void* const* d_in, const int* in_sizes, int n_in,
                              void* d_out, int out_size)
{
    const float* input_feat = (const float*)d_in[0];  // [4,64,128,128]
    const float* inter      = (const float*)d_in[1];  // [4,64,128,128]
    const float* weight     = (const float*)d_in[2];  // [128,64,3,3]
    const float* bias       = (const float*)d_in[3];  // [128]
    const float* w_om       = (const float*)d_in[4];  // [27,128,3,3]
    const float* b_om       = (const float*)d_in[5];  // [27]
    float* out = (float*)d_out;                       // [4,128,128,128]

    k_prep<<<288, 256>>>(weight, w_om);
    k_prep_feat<<<4096, 256>>>(input_feat, inter);
    k_offconv_mma<<<dim3(128, 4), 256>>>(b_om);
    k_deform_mma<<<dim3(128, 4), 256>>>(input_feat, bias, out);
}